// round 14
// baseline (speedup 1.0000x reference)
#include <cuda_runtime.h>
#include <cuda_bf16.h>
#include <cuda_fp16.h>
#include <math.h>

#define NMAX 50000
#define EMAX 1000000
#define HC 256            // H*C
#define HEADS 4
#define NEG_SLOPE 0.2f
#define BN_EPS 1e-5f
#define NB 128            // CSR blocks inside the fused kernel (<=148: wave-1 safe)

// ---------------- scratch (static device globals; no allocation) ----------------
__device__ __align__(16) __half g_xh[NMAX * HC];      // projected features (fp16)
__device__ __align__(16) __half g_h[NMAX * HC];       // h (pre-BN, fp16)
__device__ __align__(16) __half g_Wt[HC * HC];        // W transposed [n][k], fp16
__device__ int    g_rank[EMAX];                        // within-row rank of each edge
__device__ __align__(8) int2  g_sd[EMAX];              // CSR: (src,dst) per slot
__device__ __align__(8) uint2 g_ex[EMAX];              // CSR: per-edge exp weights (4 heads, fp16x4)
__device__ int    g_count[NMAX];
__device__ int    g_rowptr[NMAX + 1];
__device__ int    g_blocksum[NB];
__device__ int    g_badflag[NB];
__device__ __align__(16) float g_asrc[NMAX * HEADS];
__device__ __align__(16) float g_adst[NMAX * HEADS];
__device__ float  g_csum[HC];
__device__ float  g_csumsq[HC];
__device__ unsigned g_bar;                             // monotonic grid barrier

__device__ __forceinline__ float lrelu(float v) {
    return v > 0.f ? v : NEG_SLOPE * v;
}
// load 8 contiguous fp16 values as floats (one 16B vector load)
__device__ __forceinline__ void load8h(const __half* p, float* f) {
    int4 r = *(const int4*)p;
    float2 fa = __half22float2(*(__half2*)&r.x);
    float2 fb = __half22float2(*(__half2*)&r.y);
    float2 fc = __half22float2(*(__half2*)&r.z);
    float2 fd = __half22float2(*(__half2*)&r.w);
    f[0] = fa.x; f[1] = fa.y; f[2] = fb.x; f[3] = fb.y;
    f[4] = fc.x; f[5] = fc.y; f[6] = fd.x; f[7] = fd.y;
}
__device__ __forceinline__ void store8h(__half* p, const float* f) {
    int4 r;
    *(__half2*)&r.x = __floats2half2_rn(f[0], f[1]);
    *(__half2*)&r.y = __floats2half2_rn(f[2], f[3]);
    *(__half2*)&r.z = __floats2half2_rn(f[4], f[5]);
    *(__half2*)&r.w = __floats2half2_rn(f[6], f[7]);
    *(int4*)p = r;
}

// grid barrier over the NB CSR blocks only (monotonic; replay-safe)
__device__ __forceinline__ void grid_sync_csr() {
    __syncthreads();
    if (threadIdx.x == 0) {
        __threadfence();
        unsigned old = atomicAdd(&g_bar, 1u);
        unsigned target = (old / NB + 1u) * NB;
        unsigned cur;
        do {
            asm volatile("ld.acquire.gpu.u32 %0, [%1];" : "=r"(cur) : "l"(&g_bar));
        } while (cur < target);
    }
    __syncthreads();
}

// ---------------- fused kernel: CSR build (blocks 0..NB-1) + GEMM (blocks NB..) ----
// Shared buffer aliased by both paths: GEMM needs 2*128*PH halves = 20480 B;
// CSR needs 2*512 ints = 4096 B.
#define PH 40
__global__ void __launch_bounds__(256) k_fused(const void* ei, int E, int N, int chunk,
                                               const float* __restrict__ A, int M) {
    __shared__ __align__(16) char smem_raw[2 * 128 * PH * 2];
    int tid = threadIdx.x;

    if (blockIdx.x < NB) {
        // =================== CSR path ===================
        int bid = blockIdx.x;
        int gtid = bid * 256 + tid;
        const int stride = NB * 256;
        int* bufA = (int*)smem_raw;          // 512 ints
        int* bufB = bufA + 512;              // 512 ints

        // P0: zero counts + BN stat accumulators; SAMPLED dtype detection
        for (int j = gtid; j < N; j += stride) g_count[j] = 0;
        if (gtid < HC) { g_csum[gtid] = 0.f; g_csumsq[gtid] = 0.f; }
        const long long* p64 = (const long long*)ei;
        int nsample = min(E, 65536);
        int bad = 0;
        for (int j = gtid; j < nsample; j += stride) {
            long long v = p64[j];
            if (v < 0 || v >= (long long)N) bad = 1;
        }
        bad = __syncthreads_or(bad);
        if (tid == 0) g_badflag[bid] = bad;
        grid_sync_csr();

        // P1: reduce dtype flags (NB flags; OR over first NB threads); histogram
        int myflag = (tid < NB) ? g_badflag[tid] : 0;
        int is32 = __syncthreads_or(myflag);
        for (int e = gtid; e < E; e += stride) {
            int d;
            if (is32) { const int* p = (const int*)ei; d = p[E + e]; }
            else      { d = (int)p64[E + e]; }
            d = min(max(d, 0), N - 1);
            g_rank[e] = atomicAdd(&g_count[d], 1);
        }
        grid_sync_csr();

        // P2: per-chunk exclusive scan (chunk <= 512), 2 elements/thread
        {
            int base = bid * chunk;
            int j0 = tid, j1 = tid + 256;
            int v0 = (j0 < chunk && base + j0 < N) ? g_count[base + j0] : 0;
            int v1 = (j1 < chunk && base + j1 < N) ? g_count[base + j1] : 0;
            bufA[j0] = v0; bufA[j1] = v1;
            __syncthreads();
            int* src = bufA; int* dst = bufB;
            #pragma unroll
            for (int off = 1; off < 512; off <<= 1) {
                dst[j0] = src[j0] + (j0 >= off ? src[j0 - off] : 0);
                dst[j1] = src[j1] + (j1 >= off ? src[j1 - off] : 0);
                __syncthreads();
                int* t = src; src = dst; dst = t;
            }
            if (j0 < chunk && base + j0 < N) g_rowptr[base + j0] = src[j0] - v0;
            if (j1 < chunk && base + j1 < N) g_rowptr[base + j1] = src[j1] - v1;
            if (tid == 255) g_blocksum[bid] = src[511];   // block total (inclusive last)
        }
        grid_sync_csr();

        // P3: scan of NB block sums (redundant per block) + apply offset
        {
            int v = (tid < NB) ? g_blocksum[tid] : 0;
            bufA[tid] = v;
            __syncthreads();
            int* src = bufA; int* dst = bufB;
            #pragma unroll
            for (int off = 1; off < NB; off <<= 1) {
                if (tid < NB) dst[tid] = src[tid] + (tid >= off ? src[tid - off] : 0);
                __syncthreads();
                int* t = src; src = dst; dst = t;
            }
            int myoff = src[bid] - g_blocksum[bid];   // exclusive prefix for this block
            int base = bid * chunk;
            for (int j = tid; j < chunk; j += 256)
                if (base + j < N) g_rowptr[base + j] += myoff;
            if (gtid == 0) g_rowptr[N] = E;
        }
        grid_sync_csr();

        // P4: scatter edges into CSR (re-decode ei; single int2 store per edge)
        for (int e = gtid; e < E; e += stride) {
            int s, d;
            if (is32) {
                const int* p = (const int*)ei;
                s = p[e]; d = p[E + e];
            } else {
                s = (int)p64[e]; d = (int)p64[E + e];
            }
            s = min(max(s, 0), N - 1);
            d = min(max(d, 0), N - 1);
            int pos = g_rowptr[d] + g_rank[e];
            g_sd[pos] = make_int2(s, d);
        }
    } else {
        // =================== GEMM path (fp16 m16n8k16) ===================
        __half* As = (__half*)smem_raw;            // 128*PH halves
        __half* Bs = As + 128 * PH;
        int g = blockIdx.x - NB;
        int bx = g & 1;                            // 2 column tiles (HC/128)
        int by = g >> 1;
        int lane = tid & 31, wid = tid >> 5;
        int warpM = wid & 3;
        int warpN = wid >> 2;
        int tr = lane >> 2;
        int tc = lane & 3;
        int rowBase = by * 128, colBase = bx * 128;
        if (rowBase >= M) return;

        float c[2][8][4];
        #pragma unroll
        for (int mt = 0; mt < 2; mt++)
            #pragma unroll
            for (int nt = 0; nt < 8; nt++)
                #pragma unroll
                for (int q = 0; q < 4; q++) c[mt][nt][q] = 0.f;

        for (int k0 = 0; k0 < 256; k0 += 32) {
            #pragma unroll
            for (int i = 0; i < 4; i++) {
                int idx = tid + i * 256;
                int r = idx >> 3;
                int kk = (idx & 7) * 4;
                float4 v = make_float4(0.f, 0.f, 0.f, 0.f);
                int gr = rowBase + r;
                if (gr < M) v = *(const float4*)&A[(size_t)gr * 256 + k0 + kk];
                __half2 h01 = __floats2half2_rn(v.x, v.y);
                __half2 h23 = __floats2half2_rn(v.z, v.w);
                uint2 pk;
                pk.x = *(unsigned*)&h01;
                pk.y = *(unsigned*)&h23;
                *(uint2*)&As[r * PH + kk] = pk;
            }
            #pragma unroll
            for (int i = 0; i < 2; i++) {
                int idx = tid + i * 256;
                int n = idx >> 2;
                int kk = (idx & 3) * 8;
                int4 v = *(const int4*)&g_Wt[(size_t)(colBase + n) * 256 + k0 + kk];
                *(int4*)&Bs[n * PH + kk] = v;
            }
            __syncthreads();
            #pragma unroll
            for (int ks = 0; ks < 2; ks++) {
                int kb = ks * 16;
                unsigned a[2][4], b[8][2];
                #pragma unroll
                for (int mt = 0; mt < 2; mt++) {
                    int m0 = warpM * 32 + mt * 16 + tr;
                    a[mt][0] = *(unsigned*)&As[m0 * PH + kb + 2 * tc];
                    a[mt][1] = *(unsigned*)&As[(m0 + 8) * PH + kb + 2 * tc];
                    a[mt][2] = *(unsigned*)&As[m0 * PH + kb + 2 * tc + 8];
                    a[mt][3] = *(unsigned*)&As[(m0 + 8) * PH + kb + 2 * tc + 8];
                }
                #pragma unroll
                for (int nt = 0; nt < 8; nt++) {
                    int n0 = warpN * 64 + nt * 8 + tr;
                    b[nt][0] = *(unsigned*)&Bs[n0 * PH + kb + 2 * tc];
                    b[nt][1] = *(unsigned*)&Bs[n0 * PH + kb + 2 * tc + 8];
                }
                #pragma unroll
                for (int mt = 0; mt < 2; mt++)
                    #pragma unroll
                    for (int nt = 0; nt < 8; nt++) {
                        asm volatile(
                            "mma.sync.aligned.m16n8k16.row.col.f32.f16.f16.f32 "
                            "{%0,%1,%2,%3}, {%4,%5,%6,%7}, {%8,%9}, {%0,%1,%2,%3};"
                            : "+f"(c[mt][nt][0]), "+f"(c[mt][nt][1]),
                              "+f"(c[mt][nt][2]), "+f"(c[mt][nt][3])
                            : "r"(a[mt][0]), "r"(a[mt][1]), "r"(a[mt][2]), "r"(a[mt][3]),
                              "r"(b[nt][0]), "r"(b[nt][1]));
                    }
            }
            __syncthreads();
        }
        #pragma unroll
        for (int mt = 0; mt < 2; mt++) {
            int m0 = rowBase + warpM * 32 + mt * 16;
            #pragma unroll
            for (int half = 0; half < 2; half++) {
                int r = m0 + tr + half * 8;
                if (r < M) {
                    __half* rowp = &g_xh[(size_t)r * 256 + colBase + warpN * 64];
                    #pragma unroll
                    for (int nt = 0; nt < 8; nt++) {
                        __half2 v = __floats2half2_rn(c[mt][nt][half * 2], c[mt][nt][half * 2 + 1]);
                        *(__half2*)&rowp[nt * 8 + 2 * tc] = v;
                    }
                }
            }
        }
    }
}

// ---------------- kernel 0b: transpose W -> fp16 [n][k] ----------------
__global__ void k_transW(const float* __restrict__ W) {
    int i = blockIdx.x * blockDim.x + threadIdx.x;   // 65536 threads
    int k = i >> 8, n = i & 255;
    g_Wt[n * 256 + k] = __float2half_rn(W[(size_t)k * 256 + n]);
}

// ---------------- kernel 2: per-node attention logits (all-vector loads) ----------------
__global__ void k_attn(const float* __restrict__ att_s, const float* __restrict__ att_d, int N) {
    int n = (blockIdx.x * blockDim.x + threadIdx.x) >> 5;
    int lane = threadIdx.x & 31;
    if (n >= N) return;
    int c0 = lane * 8;
    float xv[8];
    load8h(g_xh + (size_t)n * 256 + c0, xv);
    float4 s0 = *(const float4*)&att_s[c0];
    float4 s1 = *(const float4*)&att_s[c0 + 4];
    float4 d0 = *(const float4*)&att_d[c0];
    float4 d1 = *(const float4*)&att_d[c0 + 4];
    float as = xv[0] * s0.x + xv[1] * s0.y + xv[2] * s0.z + xv[3] * s0.w
             + xv[4] * s1.x + xv[5] * s1.y + xv[6] * s1.z + xv[7] * s1.w;
    float ad = xv[0] * d0.x + xv[1] * d0.y + xv[2] * d0.z + xv[3] * d0.w
             + xv[4] * d1.x + xv[5] * d1.y + xv[6] * d1.z + xv[7] * d1.w;
    #pragma unroll
    for (int off = 1; off < 8; off <<= 1) {
        as += __shfl_xor_sync(0xffffffffu, as, off);
        ad += __shfl_xor_sync(0xffffffffu, ad, off);
    }
    if ((lane & 7) == 0) {
        int h = lane >> 3;
        g_asrc[n * HEADS + h] = as;
        g_adst[n * HEADS + h] = ad;
    }
}

// ---------------- kernel 2b: per-edge exp weights (fp16x4, CSR order) ----------------
__global__ void k_edge_exp(int E) {
    int i = blockIdx.x * blockDim.x + threadIdx.x;
    if (i >= E) return;
    int2 sd = g_sd[i];
    float4 as4 = *(const float4*)&g_asrc[sd.x * HEADS];
    float4 ad4 = *(const float4*)&g_adst[sd.y * HEADS];
    uint2 packed;
    *(__half2*)&packed.x = __floats2half2_rn(__expf(lrelu(as4.x + ad4.x)),
                                             __expf(lrelu(as4.y + ad4.y)));
    *(__half2*)&packed.y = __floats2half2_rn(__expf(lrelu(as4.z + ad4.z)),
                                             __expf(lrelu(as4.w + ad4.w)));
    g_ex[i] = packed;
}

// ---------------- kernel 3: aggregation (fp16 gathers, fp32 accumulation) ----------------
__global__ void __launch_bounds__(256) k_aggregate(const float* __restrict__ bias, int N) {
    int n = (blockIdx.x * blockDim.x + threadIdx.x) >> 5;
    int lane = threadIdx.x & 31;
    if (n >= N) return;
    int row0 = g_rowptr[n];
    int deg  = g_rowptr[n + 1] - row0;
    int myhead = lane >> 3;

    float acc[8] = {};
    float denom = 0.f;

    int i = 0;
    for (; i + 2 <= deg; i += 2) {
        int s0 = g_sd[row0 + i].x;
        int s1 = g_sd[row0 + i + 1].x;
        uint2 p0 = g_ex[row0 + i];
        uint2 p1 = g_ex[row0 + i + 1];
        float2 e0a = __half22float2(*(__half2*)&p0.x);
        float2 e0b = __half22float2(*(__half2*)&p0.y);
        float2 e1a = __half22float2(*(__half2*)&p1.x);
        float2 e1b = __half22float2(*(__half2*)&p1.y);
        float ex0 = myhead == 0 ? e0a.x : myhead == 1 ? e0a.y : myhead == 2 ? e0b.x : e0b.y;
        float ex1 = myhead == 0 ? e1a.x : myhead == 1 ? e1a.y : myhead == 2 ? e1b.x : e1b.y;
        denom += ex0 + ex1;
        float x0[8], x1[8];
        load8h(g_xh + (size_t)s0 * 256 + lane * 8, x0);
        load8h(g_xh + (size_t)s1 * 256 + lane * 8, x1);
        #pragma unroll
        for (int q = 0; q < 8; q++) acc[q] += ex0 * x0[q] + ex1 * x1[q];
    }
    if (i < deg) {
        int s0 = g_sd[row0 + i].x;
        uint2 p0 = g_ex[row0 + i];
        float2 e0a = __half22float2(*(__half2*)&p0.x);
        float2 e0b = __half22float2(*(__half2*)&p0.y);
        float ex0 = myhead == 0 ? e0a.x : myhead == 1 ? e0a.y : myhead == 2 ? e0b.x : e0b.y;
        denom += ex0;
        float x0[8];
        load8h(g_xh + (size_t)s0 * 256 + lane * 8, x0);
        #pragma unroll
        for (int q = 0; q < 8; q++) acc[q] += ex0 * x0[q];
    }

    // self-loop (fp32 denominator)
    float asv = g_asrc[n * HEADS + myhead];
    float adv = g_adst[n * HEADS + myhead];
    float exself = __expf(lrelu(asv + adv));
    {
        float xs[8];
        load8h(g_xh + (size_t)n * 256 + lane * 8, xs);
        #pragma unroll
        for (int q = 0; q < 8; q++) acc[q] += exself * xs[q];
    }
    float inv = 1.f / (denom + exself);

    int c0 = lane * 8;
    float4 bb0 = *(const float4*)&bias[c0];
    float4 bb1 = *(const float4*)&bias[c0 + 4];
    float hv[8];
    hv[0] = acc[0] * inv + bb0.x; hv[1] = acc[1] * inv + bb0.y;
    hv[2] = acc[2] * inv + bb0.z; hv[3] = acc[3] * inv + bb0.w;
    hv[4] = acc[4] * inv + bb1.x; hv[5] = acc[5] * inv + bb1.y;
    hv[6] = acc[6] * inv + bb1.z; hv[7] = acc[7] * inv + bb1.w;
    store8h(g_h + (size_t)n * 256 + c0, hv);
}

// ---------------- kernel 5: batchnorm statistics (vectorized int4 loads) ----------------
#define BN_BLOCKS 32
__global__ void __launch_bounds__(256) k_bnstats(int N) {
    int tid = threadIdx.x;
    int c0 = (tid & 31) * 8;              // 8 channels per lane
    int rw = tid >> 5;                    // 0..7
    int rows = (N + BN_BLOCKS - 1) / BN_BLOCKS;
    int n0 = blockIdx.x * rows;
    int n1 = min(n0 + rows, N);
    float s[8] = {}, sq[8] = {};
    for (int n = n0 + rw; n < n1; n += 8) {
        float v[8];
        load8h(g_h + (size_t)n * 256 + c0, v);
        #pragma unroll
        for (int q = 0; q < 8; q++) { s[q] += v[q]; sq[q] += v[q] * v[q]; }
    }
    #pragma unroll
    for (int q = 0; q < 8; q++) {
        atomicAdd(&g_csum[c0 + q], s[q]);
        atomicAdd(&g_csumsq[c0 + q], sq[q]);
    }
}

// ---------------- kernel 6: BN + ELU + residual ----------------
__global__ void k_final(const float* __restrict__ feature,
                        const float* __restrict__ gamma,
                        const float* __restrict__ beta,
                        float* __restrict__ out, int N) {
    int i = blockIdx.x * blockDim.x + threadIdx.x;
    int total = N * HC;
    if (i >= total) return;
    int c = i & 255;
    float invN = 1.f / (float)N;
    float mu = g_csum[c] * invN;
    float var = g_csumsq[c] * invN - mu * mu;
    float rstd = rsqrtf(var + BN_EPS);
    float hval = (__half2float(g_h[i]) - mu) * rstd * gamma[c] + beta[c];
    hval = hval > 0.f ? hval : (expf(hval) - 1.f);
    out[i] = feature[i] + hval;
}

// ---------------- launch ----------------
extern "C" void kernel_launch(void* const* d_in, const int* in_sizes, int n_in,
                              void* d_out, int out_size) {
    int idx_feat = 0, idx_edge = 0, idx_W = 0;
    int small[8]; int nsmall = 0;
    long long max1 = -1, max2 = -1;
    for (int i = 0; i < n_in; i++) {
        long long s = in_sizes[i];
        if (s > max1) { max2 = max1; max1 = s; }
        else if (s > max2) { max2 = s; }
    }
    for (int i = 0; i < n_in; i++) {
        long long s = in_sizes[i];
        if (s == max1) idx_feat = i;
        else if (s == max2) idx_edge = i;
        else if (s == 65536) idx_W = i;
        else if (nsmall < 8) small[nsmall++] = i;
    }
    int i_asrc, i_adst, i_bias, i_gamma, i_beta;
    if (idx_feat == 0) {
        i_asrc = small[0]; i_adst = small[1];
        i_bias = small[2]; i_gamma = small[3]; i_beta = small[4];
    } else {
        i_adst = small[0]; i_asrc = small[1];
        i_beta = small[2]; i_bias = small[3]; i_gamma = small[4];
    }

    const float* feature = (const float*)d_in[idx_feat];
    const void*  ei      = (const void*)d_in[idx_edge];
    const float* W       = (const float*)d_in[idx_W];
    const float* att_src = (const float*)d_in[i_asrc];
    const float* att_dst = (const float*)d_in[i_adst];
    const float* bias    = (const float*)d_in[i_bias];
    const float* gamma   = (const float*)d_in[i_gamma];
    const float* beta    = (const float*)d_in[i_beta];
    float* out = (float*)d_out;

    int N = (int)(max1 / HC);
    int E = (int)(max2 / 2);
    if (E > EMAX) E = EMAX;
    int chunk = (N + NB - 1) / NB;   // <= 512 for N <= 65536

    k_transW<<<256, 256>>>(W);

    // fused CSR + GEMM: blocks [0,NB) build CSR; the rest do GEMM tiles
    int gemmBlocks = 2 * ((N + 127) / 128);
    k_fused<<<NB + gemmBlocks, 256>>>(ei, E, N, chunk, feature, N);

    k_attn<<<(N * 32 + 255) / 256, 256>>>(att_src, att_dst, N);
    k_edge_exp<<<(E + 255) / 256, 256>>>(E);
    k_aggregate<<<(N * 32 + 255) / 256, 256>>>(bias, N);
    k_bnstats<<<BN_BLOCKS, 256>>>(N);
    k_final<<<(N * HC + 255) / 256, 256>>>(feature, gamma, beta, out, N);
}

// round 15
// speedup vs baseline: 1.0686x; 1.0686x over previous
#include <cuda_runtime.h>
#include <cuda_bf16.h>
#include <cuda_fp16.h>
#include <math.h>

#define NMAX 50000
#define EMAX 1000000
#define HC 256            // H*C
#define HEADS 4
#define NEG_SLOPE 0.2f
#define BN_EPS 1e-5f
#define NB 256            // blocks in the CSR mega-kernel

// ---------------- scratch (static device globals; no allocation) ----------------
__device__ __align__(16) __half g_xh[NMAX * HC];      // projected features (fp16)
__device__ __align__(16) __half g_h[NMAX * HC];       // h (pre-BN, fp16)
__device__ __align__(16) __half g_Wt[HC * HC];        // W transposed [n][k], fp16
__device__ int    g_rank[EMAX];                        // within-row rank of each edge
__device__ __align__(8) int2  g_sd[EMAX];              // CSR: (src,dst) per slot
__device__ __align__(8) uint2 g_ex[EMAX];              // CSR: per-edge exp weights (4 heads, fp16x4)
__device__ int    g_count[NMAX];
__device__ int    g_rowptr[NMAX + 1];
__device__ int    g_blocksum[NB];
__device__ int    g_badflag[NB];
__device__ __align__(16) float g_asrc[NMAX * HEADS];
__device__ __align__(16) float g_adst[NMAX * HEADS];
__device__ float  g_csum[HC];
__device__ float  g_csumsq[HC];
__device__ unsigned g_bar;                             // monotonic grid barrier

__device__ __forceinline__ float lrelu(float v) {
    return v > 0.f ? v : NEG_SLOPE * v;
}
// load 8 contiguous fp16 values as floats (one 16B vector load)
__device__ __forceinline__ void load8h(const __half* p, float* f) {
    int4 r = *(const int4*)p;
    float2 fa = __half22float2(*(__half2*)&r.x);
    float2 fb = __half22float2(*(__half2*)&r.y);
    float2 fc = __half22float2(*(__half2*)&r.z);
    float2 fd = __half22float2(*(__half2*)&r.w);
    f[0] = fa.x; f[1] = fa.y; f[2] = fb.x; f[3] = fb.y;
    f[4] = fc.x; f[5] = fc.y; f[6] = fd.x; f[7] = fd.y;
}
__device__ __forceinline__ void store8h(__half* p, const float* f) {
    int4 r;
    *(__half2*)&r.x = __floats2half2_rn(f[0], f[1]);
    *(__half2*)&r.y = __floats2half2_rn(f[2], f[3]);
    *(__half2*)&r.z = __floats2half2_rn(f[4], f[5]);
    *(__half2*)&r.w = __floats2half2_rn(f[6], f[7]);
    *(int4*)p = r;
}

// grid-wide barrier: monotonic counter; each call adds a fixed multiple of NB
// arrivals, so the counter stays aligned across graph replays.
__device__ __forceinline__ void grid_sync() {
    __syncthreads();
    if (threadIdx.x == 0) {
        __threadfence();
        unsigned old = atomicAdd(&g_bar, 1u);
        unsigned target = (old / NB + 1u) * NB;
        unsigned cur;
        do {
            asm volatile("ld.acquire.gpu.u32 %0, [%1];" : "=r"(cur) : "l"(&g_bar));
        } while (cur < target);
    }
    __syncthreads();
}

// ---------------- CSR mega-kernel: init+detect+transW+decode+scan+scatter ------
__global__ void __launch_bounds__(256) k_csr(const void* ei, int E, int N, int chunk,
                                             const float* __restrict__ W) {
    int tid = threadIdx.x, bid = blockIdx.x;
    int gtid = bid * 256 + tid;
    const int stride = NB * 256;

    // P0: zero counts + BN stats; transpose W -> fp16; SAMPLED dtype detection
    for (int j = gtid; j < N; j += stride) g_count[j] = 0;
    if (gtid < HC) { g_csum[gtid] = 0.f; g_csumsq[gtid] = 0.f; }
    for (int j = gtid; j < HC * HC; j += stride) {
        int k = j >> 8, n = j & 255;
        g_Wt[n * 256 + k] = __float2half_rn(W[(size_t)k * 256 + n]);
    }
    const long long* p64 = (const long long*)ei;
    int nsample = min(E, 65536);
    int bad = 0;
    for (int j = gtid; j < nsample; j += stride) {
        long long v = p64[j];
        if (v < 0 || v >= (long long)N) bad = 1;
    }
    bad = __syncthreads_or(bad);
    if (tid == 0) g_badflag[bid] = bad;
    grid_sync();

    // P1: reduce dtype flags; dst histogram (rank saved)
    int is32 = __syncthreads_or(g_badflag[tid]);
    for (int e = gtid; e < E; e += stride) {
        int d;
        if (is32) { const int* p = (const int*)ei; d = p[E + e]; }
        else      { d = (int)p64[E + e]; }
        d = min(max(d, 0), N - 1);
        g_rank[e] = atomicAdd(&g_count[d], 1);
    }
    grid_sync();

    // P2: per-chunk exclusive scan of counts
    {
        __shared__ int sh[256];
        int base = bid * chunk;
        int i = base + tid;
        int v = (tid < chunk && i < N) ? g_count[i] : 0;
        sh[tid] = v;
        __syncthreads();
        #pragma unroll
        for (int off = 1; off < 256; off <<= 1) {
            int t = (tid >= off) ? sh[tid - off] : 0;
            __syncthreads();
            sh[tid] += t;
            __syncthreads();
        }
        if (tid < chunk && i < N) g_rowptr[i] = sh[tid] - v;
        if (tid == 255) g_blocksum[bid] = sh[255];
    }
    grid_sync();

    // P3: redundant block-sum scan + offset apply
    {
        __shared__ int sh[256], orig[256];
        int v = g_blocksum[tid];
        sh[tid] = v; orig[tid] = v;
        __syncthreads();
        #pragma unroll
        for (int off = 1; off < 256; off <<= 1) {
            int t = (tid >= off) ? sh[tid - off] : 0;
            __syncthreads();
            sh[tid] += t;
            __syncthreads();
        }
        int myoff = sh[bid] - orig[bid];
        int base = bid * chunk;
        if (tid < chunk && base + tid < N) g_rowptr[base + tid] += myoff;
        if (gtid == 0) g_rowptr[N] = E;
    }
    grid_sync();

    // P4: scatter edges into CSR (re-decode ei; single int2 store per edge)
    for (int e = gtid; e < E; e += stride) {
        int s, d;
        if (is32) {
            const int* p = (const int*)ei;
            s = p[e]; d = p[E + e];
        } else {
            s = (int)p64[e]; d = (int)p64[E + e];
        }
        s = min(max(s, 0), N - 1);
        d = min(max(d, 0), N - 1);
        int pos = g_rowptr[d] + g_rank[e];
        g_sd[pos] = make_int2(s, d);
    }
}

// ---------------- kernel 1: FP16 MMA GEMM with register double-buffering --------
// 128x128 block tile, BK=32, 8 warps (4M x 2N), warp tile 32x64.
// As[row][k], Bs[n][k], pitch 40 halves (80B): frag banks = 20*tr + tc, all distinct.
// Next k-tile's global loads issue before the current tile's MMAs (latency hiding).
#define PH 40
__global__ void __launch_bounds__(256) k_gemm(const float* __restrict__ A, int M) {
    __shared__ __half As[128 * PH];
    __shared__ __half Bs[128 * PH];
    int tid = threadIdx.x;
    int lane = tid & 31, wid = tid >> 5;
    int warpM = wid & 3;          // 0..3 -> 32 rows each
    int warpN = wid >> 2;         // 0..1 -> 64 cols each
    int tr = lane >> 2;           // 0..7
    int tc = lane & 3;            // 0..3
    int rowBase = blockIdx.y * 128, colBase = blockIdx.x * 128;

    // per-thread tile-load coordinates (fixed across k-iterations)
    int ar[4], ak[4];
    #pragma unroll
    for (int i = 0; i < 4; i++) {
        int idx = tid + i * 256;          // 0..1023
        ar[i] = idx >> 3;                 // 0..127
        ak[i] = (idx & 7) * 4;            // 0,4,...,28
    }
    int bn[2], bk[2];
    #pragma unroll
    for (int i = 0; i < 2; i++) {
        int idx = tid + i * 256;          // 0..511
        bn[i] = idx >> 2;                 // 0..127
        bk[i] = (idx & 3) * 8;            // 0,8,16,24
    }

    float c[2][8][4];
    #pragma unroll
    for (int mt = 0; mt < 2; mt++)
        #pragma unroll
        for (int nt = 0; nt < 8; nt++)
            #pragma unroll
            for (int q = 0; q < 4; q++) c[mt][nt][q] = 0.f;

    // prologue: load tile k0=0 into registers
    float4 pa[4];
    int4 pb[2];
    #pragma unroll
    for (int i = 0; i < 4; i++) {
        pa[i] = make_float4(0.f, 0.f, 0.f, 0.f);
        int gr = rowBase + ar[i];
        if (gr < M) pa[i] = *(const float4*)&A[(size_t)gr * 256 + ak[i]];
    }
    #pragma unroll
    for (int i = 0; i < 2; i++)
        pb[i] = *(const int4*)&g_Wt[(size_t)(colBase + bn[i]) * 256 + bk[i]];

    for (int k0 = 0; k0 < 256; k0 += 32) {
        // store prefetched tile to smem (with fp32->fp16 conversion for A)
        #pragma unroll
        for (int i = 0; i < 4; i++) {
            __half2 h01 = __floats2half2_rn(pa[i].x, pa[i].y);
            __half2 h23 = __floats2half2_rn(pa[i].z, pa[i].w);
            uint2 pk;
            pk.x = *(unsigned*)&h01;
            pk.y = *(unsigned*)&h23;
            *(uint2*)&As[ar[i] * PH + ak[i]] = pk;
        }
        #pragma unroll
        for (int i = 0; i < 2; i++)
            *(int4*)&Bs[bn[i] * PH + bk[i]] = pb[i];
        __syncthreads();

        // prefetch NEXT tile into registers (overlaps with MMAs below)
        int kn = k0 + 32;
        if (kn < 256) {
            #pragma unroll
            for (int i = 0; i < 4; i++) {
                pa[i] = make_float4(0.f, 0.f, 0.f, 0.f);
                int gr = rowBase + ar[i];
                if (gr < M) pa[i] = *(const float4*)&A[(size_t)gr * 256 + kn + ak[i]];
            }
            #pragma unroll
            for (int i = 0; i < 2; i++)
                pb[i] = *(const int4*)&g_Wt[(size_t)(colBase + bn[i]) * 256 + kn + bk[i]];
        }

        #pragma unroll
        for (int ks = 0; ks < 2; ks++) {
            int kb = ks * 16;
            unsigned a[2][4], b[8][2];
            #pragma unroll
            for (int mt = 0; mt < 2; mt++) {
                int m0 = warpM * 32 + mt * 16 + tr;
                a[mt][0] = *(unsigned*)&As[m0 * PH + kb + 2 * tc];
                a[mt][1] = *(unsigned*)&As[(m0 + 8) * PH + kb + 2 * tc];
                a[mt][2] = *(unsigned*)&As[m0 * PH + kb + 2 * tc + 8];
                a[mt][3] = *(unsigned*)&As[(m0 + 8) * PH + kb + 2 * tc + 8];
            }
            #pragma unroll
            for (int nt = 0; nt < 8; nt++) {
                int n0 = warpN * 64 + nt * 8 + tr;
                b[nt][0] = *(unsigned*)&Bs[n0 * PH + kb + 2 * tc];
                b[nt][1] = *(unsigned*)&Bs[n0 * PH + kb + 2 * tc + 8];
            }
            #pragma unroll
            for (int mt = 0; mt < 2; mt++)
                #pragma unroll
                for (int nt = 0; nt < 8; nt++) {
                    asm volatile(
                        "mma.sync.aligned.m16n8k16.row.col.f32.f16.f16.f32 "
                        "{%0,%1,%2,%3}, {%4,%5,%6,%7}, {%8,%9}, {%0,%1,%2,%3};"
                        : "+f"(c[mt][nt][0]), "+f"(c[mt][nt][1]),
                          "+f"(c[mt][nt][2]), "+f"(c[mt][nt][3])
                        : "r"(a[mt][0]), "r"(a[mt][1]), "r"(a[mt][2]), "r"(a[mt][3]),
                          "r"(b[nt][0]), "r"(b[nt][1]));
                }
        }
        __syncthreads();
    }
    #pragma unroll
    for (int mt = 0; mt < 2; mt++) {
        int m0 = rowBase + warpM * 32 + mt * 16;
        #pragma unroll
        for (int half = 0; half < 2; half++) {
            int r = m0 + tr + half * 8;
            if (r < M) {
                __half* rowp = &g_xh[(size_t)r * 256 + colBase + warpN * 64];
                #pragma unroll
                for (int nt = 0; nt < 8; nt++) {
                    __half2 v = __floats2half2_rn(c[mt][nt][half * 2], c[mt][nt][half * 2 + 1]);
                    *(__half2*)&rowp[nt * 8 + 2 * tc] = v;
                }
            }
        }
    }
}

// ---------------- kernel 2: per-node attention logits (all-vector loads) ----------------
__global__ void k_attn(const float* __restrict__ att_s, const float* __restrict__ att_d, int N) {
    int n = (blockIdx.x * blockDim.x + threadIdx.x) >> 5;
    int lane = threadIdx.x & 31;
    if (n >= N) return;
    int c0 = lane * 8;
    float xv[8];
    load8h(g_xh + (size_t)n * 256 + c0, xv);
    float4 s0 = *(const float4*)&att_s[c0];
    float4 s1 = *(const float4*)&att_s[c0 + 4];
    float4 d0 = *(const float4*)&att_d[c0];
    float4 d1 = *(const float4*)&att_d[c0 + 4];
    float as = xv[0] * s0.x + xv[1] * s0.y + xv[2] * s0.z + xv[3] * s0.w
             + xv[4] * s1.x + xv[5] * s1.y + xv[6] * s1.z + xv[7] * s1.w;
    float ad = xv[0] * d0.x + xv[1] * d0.y + xv[2] * d0.z + xv[3] * d0.w
             + xv[4] * d1.x + xv[5] * d1.y + xv[6] * d1.z + xv[7] * d1.w;
    #pragma unroll
    for (int off = 1; off < 8; off <<= 1) {
        as += __shfl_xor_sync(0xffffffffu, as, off);
        ad += __shfl_xor_sync(0xffffffffu, ad, off);
    }
    if ((lane & 7) == 0) {
        int h = lane >> 3;
        g_asrc[n * HEADS + h] = as;
        g_adst[n * HEADS + h] = ad;
    }
}

// ---------------- kernel 2b: per-edge exp weights (fp16x4, CSR order) ----------------
__global__ void k_edge_exp(int E) {
    int i = blockIdx.x * blockDim.x + threadIdx.x;
    if (i >= E) return;
    int2 sd = g_sd[i];
    float4 as4 = *(const float4*)&g_asrc[sd.x * HEADS];
    float4 ad4 = *(const float4*)&g_adst[sd.y * HEADS];
    uint2 packed;
    *(__half2*)&packed.x = __floats2half2_rn(__expf(lrelu(as4.x + ad4.x)),
                                             __expf(lrelu(as4.y + ad4.y)));
    *(__half2*)&packed.y = __floats2half2_rn(__expf(lrelu(as4.z + ad4.z)),
                                             __expf(lrelu(as4.w + ad4.w)));
    g_ex[i] = packed;
}

// ---------------- kernel 3: aggregation (fp16 gathers, fp32 accumulation) ----------------
__global__ void __launch_bounds__(256) k_aggregate(const float* __restrict__ bias, int N) {
    int n = (blockIdx.x * blockDim.x + threadIdx.x) >> 5;
    int lane = threadIdx.x & 31;
    if (n >= N) return;
    int row0 = g_rowptr[n];
    int deg  = g_rowptr[n + 1] - row0;
    int myhead = lane >> 3;

    float acc[8] = {};
    float denom = 0.f;

    int i = 0;
    for (; i + 2 <= deg; i += 2) {
        int s0 = g_sd[row0 + i].x;
        int s1 = g_sd[row0 + i + 1].x;
        uint2 p0 = g_ex[row0 + i];
        uint2 p1 = g_ex[row0 + i + 1];
        float2 e0a = __half22float2(*(__half2*)&p0.x);
        float2 e0b = __half22float2(*(__half2*)&p0.y);
        float2 e1a = __half22float2(*(__half2*)&p1.x);
        float2 e1b = __half22float2(*(__half2*)&p1.y);
        float ex0 = myhead == 0 ? e0a.x : myhead == 1 ? e0a.y : myhead == 2 ? e0b.x : e0b.y;
        float ex1 = myhead == 0 ? e1a.x : myhead == 1 ? e1a.y : myhead == 2 ? e1b.x : e1b.y;
        denom += ex0 + ex1;
        float x0[8], x1[8];
        load8h(g_xh + (size_t)s0 * 256 + lane * 8, x0);
        load8h(g_xh + (size_t)s1 * 256 + lane * 8, x1);
        #pragma unroll
        for (int q = 0; q < 8; q++) acc[q] += ex0 * x0[q] + ex1 * x1[q];
    }
    if (i < deg) {
        int s0 = g_sd[row0 + i].x;
        uint2 p0 = g_ex[row0 + i];
        float2 e0a = __half22float2(*(__half2*)&p0.x);
        float2 e0b = __half22float2(*(__half2*)&p0.y);
        float ex0 = myhead == 0 ? e0a.x : myhead == 1 ? e0a.y : myhead == 2 ? e0b.x : e0b.y;
        denom += ex0;
        float x0[8];
        load8h(g_xh + (size_t)s0 * 256 + lane * 8, x0);
        #pragma unroll
        for (int q = 0; q < 8; q++) acc[q] += ex0 * x0[q];
    }

    // self-loop (fp32 denominator)
    float asv = g_asrc[n * HEADS + myhead];
    float adv = g_adst[n * HEADS + myhead];
    float exself = __expf(lrelu(asv + adv));
    {
        float xs[8];
        load8h(g_xh + (size_t)n * 256 + lane * 8, xs);
        #pragma unroll
        for (int q = 0; q < 8; q++) acc[q] += exself * xs[q];
    }
    float inv = 1.f / (denom + exself);

    int c0 = lane * 8;
    float4 bb0 = *(const float4*)&bias[c0];
    float4 bb1 = *(const float4*)&bias[c0 + 4];
    float hv[8];
    hv[0] = acc[0] * inv + bb0.x; hv[1] = acc[1] * inv + bb0.y;
    hv[2] = acc[2] * inv + bb0.z; hv[3] = acc[3] * inv + bb0.w;
    hv[4] = acc[4] * inv + bb1.x; hv[5] = acc[5] * inv + bb1.y;
    hv[6] = acc[6] * inv + bb1.z; hv[7] = acc[7] * inv + bb1.w;
    store8h(g_h + (size_t)n * 256 + c0, hv);
}

// ---------------- kernel 5: batchnorm statistics (vectorized int4 loads) ----------------
#define BN_BLOCKS 32
__global__ void __launch_bounds__(256) k_bnstats(int N) {
    int tid = threadIdx.x;
    int c0 = (tid & 31) * 8;              // 8 channels per lane
    int rw = tid >> 5;                    // 0..7
    int rows = (N + BN_BLOCKS - 1) / BN_BLOCKS;
    int n0 = blockIdx.x * rows;
    int n1 = min(n0 + rows, N);
    float s[8] = {}, sq[8] = {};
    for (int n = n0 + rw; n < n1; n += 8) {
        float v[8];
        load8h(g_h + (size_t)n * 256 + c0, v);
        #pragma unroll
        for (int q = 0; q < 8; q++) { s[q] += v[q]; sq[q] += v[q] * v[q]; }
    }
    #pragma unroll
    for (int q = 0; q < 8; q++) {
        atomicAdd(&g_csum[c0 + q], s[q]);
        atomicAdd(&g_csumsq[c0 + q], sq[q]);
    }
}

// ---------------- kernel 6: BN + ELU + residual ----------------
__global__ void k_final(const float* __restrict__ feature,
                        const float* __restrict__ gamma,
                        const float* __restrict__ beta,
                        float* __restrict__ out, int N) {
    int i = blockIdx.x * blockDim.x + threadIdx.x;
    int total = N * HC;
    if (i >= total) return;
    int c = i & 255;
    float invN = 1.f / (float)N;
    float mu = g_csum[c] * invN;
    float var = g_csumsq[c] * invN - mu * mu;
    float rstd = rsqrtf(var + BN_EPS);
    float hval = (__half2float(g_h[i]) - mu) * rstd * gamma[c] + beta[c];
    hval = hval > 0.f ? hval : (expf(hval) - 1.f);
    out[i] = feature[i] + hval;
}

// ---------------- launch ----------------
extern "C" void kernel_launch(void* const* d_in, const int* in_sizes, int n_in,
                              void* d_out, int out_size) {
    int idx_feat = 0, idx_edge = 0, idx_W = 0;
    int small[8]; int nsmall = 0;
    long long max1 = -1, max2 = -1;
    for (int i = 0; i < n_in; i++) {
        long long s = in_sizes[i];
        if (s > max1) { max2 = max1; max1 = s; }
        else if (s > max2) { max2 = s; }
    }
    for (int i = 0; i < n_in; i++) {
        long long s = in_sizes[i];
        if (s == max1) idx_feat = i;
        else if (s == max2) idx_edge = i;
        else if (s == 65536) idx_W = i;
        else if (nsmall < 8) small[nsmall++] = i;
    }
    int i_asrc, i_adst, i_bias, i_gamma, i_beta;
    if (idx_feat == 0) {
        i_asrc = small[0]; i_adst = small[1];
        i_bias = small[2]; i_gamma = small[3]; i_beta = small[4];
    } else {
        i_adst = small[0]; i_asrc = small[1];
        i_beta = small[2]; i_bias = small[3]; i_gamma = small[4];
    }

    const float* feature = (const float*)d_in[idx_feat];
    const void*  ei      = (const void*)d_in[idx_edge];
    const float* W       = (const float*)d_in[idx_W];
    const float* att_src = (const float*)d_in[i_asrc];
    const float* att_dst = (const float*)d_in[i_adst];
    const float* bias    = (const float*)d_in[i_bias];
    const float* gamma   = (const float*)d_in[i_gamma];
    const float* beta    = (const float*)d_in[i_beta];
    float* out = (float*)d_out;

    int N = (int)(max1 / HC);
    int E = (int)(max2 / 2);
    if (E > EMAX) E = EMAX;
    int chunk = (N + NB - 1) / NB;

    k_csr<<<NB, 256>>>(ei, E, N, chunk, W);

    dim3 gg(HC / 128, (N + 127) / 128);
    k_gemm<<<gg, 256>>>(feature, N);
    k_attn<<<(N * 32 + 255) / 256, 256>>>(att_src, att_dst, N);
    k_edge_exp<<<(E + 255) / 256, 256>>>(E);
    k_aggregate<<<(N * 32 + 255) / 256, 256>>>(bias, N);
    k_bnstats<<<BN_BLOCKS, 256>>>(N);
    k_final<<<(N * HC + 255) / 256, 256>>>(feature, gamma, beta, out, N);
}